// round 10
// baseline (speedup 1.0000x reference)
#include <cuda_runtime.h>
#include <math.h>

// ---------------------------------------------------------------------------
// Frequency-domain partitioned convolution (uniform overlap-save), v4.
//   v3 + (a) h folded into the z launch (one zh_kernel, extra grid row),
//        (b) y's spectral MAC fused with the first inverse FFT stage:
//            accumulate each contiguous quad in registers, butterfly, then
//            store — one fewer 128KB smem round trip and one fewer sync.
//   Register-staged radix-16 passes, MUFU twiddles, 1024 thr/CTA, padded smem.
// ---------------------------------------------------------------------------

#define T_LEN   441000
#define PAIRS   16
#define IR_LEN  44100
#define P_HOP   8192
#define NFFT    16384
#define NBLK    54          // ceil(441000 / 8192)
#define NPART   6           // ceil(44100 / 8192)
#define NT      1024

__device__ __align__(16) float2 g_H[NPART][NFFT];
__device__ __align__(16) float2 g_Z[PAIRS][NBLK][NFFT];

__device__ __forceinline__ int PADi(int i) { return i + (i >> 4); }
#define SMEM_F2 (NFFT + (NFFT >> 4))        // padded float2 count

// ---------------- complex helpers ----------------
__device__ __forceinline__ float2 cadd(float2 a, float2 b) { return make_float2(a.x + b.x, a.y + b.y); }
__device__ __forceinline__ float2 csub(float2 a, float2 b) { return make_float2(a.x - b.x, a.y - b.y); }
__device__ __forceinline__ float2 cmul(float2 a, float2 b) {
    return make_float2(fmaf(a.x, b.x, -a.y * b.y), fmaf(a.x, b.y, a.y * b.x));
}
// a * conj(b)
__device__ __forceinline__ float2 cmulc(float2 a, float2 b) {
    return make_float2(fmaf(a.x, b.x, a.y * b.y), fmaf(a.y, b.x, -a.x * b.y));
}
__device__ __forceinline__ float2 sincosw(float ang) {
    float2 w; __sincosf(ang, &w.y, &w.x); return w;   // w = (cos, sin)
}
__device__ __forceinline__ void tw_pow(float2 w1, float2& w2, float2& w3) {
    w2 = cmul(w1, w1); w3 = cmul(w2, w1);
}

// ---------------- radix-4 butterflies ----------------
__device__ __forceinline__ void bfly_fwd_w(float2& a, float2& b, float2& c, float2& d,
                                           float2 w1, float2 w2, float2 w3) {
    float2 u0 = cadd(a, c), u1 = csub(a, c), u2 = cadd(b, d), t = csub(b, d);
    float2 u3 = make_float2(t.y, -t.x);   // -i*(b-d)
    a = cadd(u0, u2);
    b = cmul(cadd(u1, u3), w1);
    c = cmul(csub(u0, u2), w2);
    d = cmul(csub(u1, u3), w3);
}
__device__ __forceinline__ void bfly_fwd_nw(float2& a, float2& b, float2& c, float2& d) {
    float2 u0 = cadd(a, c), u1 = csub(a, c), u2 = cadd(b, d), t = csub(b, d);
    float2 u3 = make_float2(t.y, -t.x);
    a = cadd(u0, u2); b = cadd(u1, u3); c = csub(u0, u2); d = csub(u1, u3);
}
__device__ __forceinline__ void bfly_inv_w(float2& a, float2& b, float2& c, float2& d,
                                           float2 w1, float2 w2, float2 w3) {
    float2 y0 = a, y1 = cmulc(b, w1), y2 = cmulc(c, w2), y3 = cmulc(d, w3);
    float2 v0 = cadd(y0, y2), v2 = csub(y0, y2);
    float2 v1 = cadd(y1, y3), v3 = csub(y1, y3);
    float2 iv3 = make_float2(-v3.y, v3.x);  // i*v3
    a = cadd(v0, v1); b = cadd(v2, iv3); c = csub(v0, v1); d = csub(v2, iv3);
}
__device__ __forceinline__ void bfly_inv_nw(float2& a, float2& b, float2& c, float2& d) {
    float2 v0 = cadd(a, c), v2 = csub(a, c);
    float2 v1 = cadd(b, d), v3 = csub(b, d);
    float2 iv3 = make_float2(-v3.y, v3.x);
    a = cadd(v0, v1); b = cadd(v2, iv3); c = csub(v0, v1); d = csub(v2, iv3);
}

// ---------------- register pass: stages S and S+1 ----------------
template<int S>
__device__ __forceinline__ void fwd_bflys(float2 v[16], int r, int mq) {
    const float c = (-6.283185307179586f / (float)NFFT) * (float)(1 << (2 * S));
    float2 w1  = sincosw(c * (float)r);
    float2 rot = sincosw(c * (float)mq);
    #pragma unroll
    for (int j1 = 0; j1 < 4; ++j1) {
        float2 w2, w3; tw_pow(w1, w2, w3);
        bfly_fwd_w(v[j1], v[j1 + 4], v[j1 + 8], v[j1 + 12], w1, w2, w3);
        if (j1 < 3) w1 = cmul(w1, rot);
    }
    float2 s1 = sincosw(4.0f * c * (float)r);
    float2 s2, s3; tw_pow(s1, s2, s3);
    #pragma unroll
    for (int q = 0; q < 4; ++q)
        bfly_fwd_w(v[4 * q], v[4 * q + 1], v[4 * q + 2], v[4 * q + 3], s1, s2, s3);
}

template<int S>
__device__ __forceinline__ void inv_bflys(float2 v[16], int r, int mq) {
    const float c = (-6.283185307179586f / (float)NFFT) * (float)(1 << (2 * S));
    float2 s1 = sincosw(4.0f * c * (float)r);
    float2 s2, s3; tw_pow(s1, s2, s3);
    #pragma unroll
    for (int q = 0; q < 4; ++q)
        bfly_inv_w(v[4 * q], v[4 * q + 1], v[4 * q + 2], v[4 * q + 3], s1, s2, s3);
    float2 w1  = sincosw(c * (float)r);
    float2 rot = sincosw(c * (float)mq);
    #pragma unroll
    for (int j1 = 0; j1 < 4; ++j1) {
        float2 w2, w3; tw_pow(w1, w2, w3);
        bfly_inv_w(v[j1], v[j1 + 4], v[j1 + 8], v[j1 + 12], w1, w2, w3);
        if (j1 < 3) w1 = cmul(w1, rot);
    }
}

template<int S>
__device__ __forceinline__ void fwd_mid_pass(float2* sm, int t) {
    const int m   = 1 << (12 - 2 * S);
    const int mq  = m >> 2;
    const int r    = t & (mq - 1);
    const int base = ((t >> (10 - 2 * S)) << (14 - 2 * S)) + r;
    float2 v[16];
    #pragma unroll
    for (int j = 0; j < 16; ++j) v[j] = sm[PADi(base + j * mq)];
    fwd_bflys<S>(v, r, mq);
    #pragma unroll
    for (int j = 0; j < 16; ++j) sm[PADi(base + j * mq)] = v[j];
}

__device__ __forceinline__ void fwd_pass0_store(float2* sm, int t, float2 v[16]) {
    fwd_bflys<0>(v, t, 1024);
    #pragma unroll
    for (int j = 0; j < 16; ++j) sm[PADi(t + j * 1024)] = v[j];
}

// Forward stage 6 (unity twiddles, contiguous quads) + store to global (scaled).
__device__ __forceinline__ void fwd_stage6_store(const float2* sm, int t,
                                                 float2* __restrict__ dst, float s) {
    float4* dst4 = (float4*)dst;
    #pragma unroll
    for (int u = 0; u < 4; ++u) {
        int a = 4 * t + 4096 * u;
        float2 va = sm[PADi(a)], vb = sm[PADi(a + 1)];
        float2 vc = sm[PADi(a + 2)], vd = sm[PADi(a + 3)];
        bfly_fwd_nw(va, vb, vc, vd);
        dst4[(a >> 1)]     = make_float4(va.x * s, va.y * s, vb.x * s, vb.y * s);
        dst4[(a >> 1) + 1] = make_float4(vc.x * s, vc.y * s, vd.x * s, vd.y * s);
    }
}

template<int S>
__device__ __forceinline__ void inv_mid_pass(float2* sm, int t) {
    const int m   = 1 << (12 - 2 * S);
    const int mq  = m >> 2;
    const int r    = t & (mq - 1);
    const int base = ((t >> (10 - 2 * S)) << (14 - 2 * S)) + r;
    float2 v[16];
    #pragma unroll
    for (int j = 0; j < 16; ++j) v[j] = sm[PADi(base + j * mq)];
    inv_bflys<S>(v, r, mq);
    #pragma unroll
    for (int j = 0; j < 16; ++j) sm[PADi(base + j * mq)] = v[j];
}

// ---------------- kernels ----------------
// Combined forward transform: rows p < PAIRS produce Z blocks from x;
// row p == PAIRS (d < NPART) produces H partitions from ir.
__global__ void __launch_bounds__(NT, 1) zh_kernel(const float* __restrict__ x,
                                                   const float* __restrict__ ir) {
    extern __shared__ float2 sm[];
    const int d = blockIdx.x;
    const int p = blockIdx.y;
    const int t = threadIdx.x;
    const bool isH = (p == PAIRS);
    if (isH && d >= NPART) return;

    float2 v[16];
    if (isH) {
        #pragma unroll
        for (int j = 0; j < 16; ++j) {
            int k = t + 1024 * j;
            int tap = d * P_HOP + k;
            float val = (k < P_HOP && tap < IR_LEN) ? ir[tap] : 0.0f;
            v[j] = make_float2(val, 0.0f);
        }
    } else {
        const int base = d * P_HOP - P_HOP;   // covers [(d-1)P, (d+1)P)
        const float* xe = x + (2 * p)     * T_LEN;
        const float* xo = x + (2 * p + 1) * T_LEN;
        #pragma unroll
        for (int j = 0; j < 16; ++j) {
            int idx = base + t + 1024 * j;
            float re = 0.0f, im = 0.0f;
            if (idx >= 0 && idx < T_LEN) { re = xe[idx]; im = xo[idx]; }
            v[j] = make_float2(re, im);
        }
    }
    fwd_pass0_store(sm, t, v);
    __syncthreads();
    fwd_mid_pass<2>(sm, t);
    __syncthreads();
    fwd_mid_pass<4>(sm, t);
    __syncthreads();
    if (isH) fwd_stage6_store(sm, t, g_H[d], 1.0f / (float)NFFT);
    else     fwd_stage6_store(sm, t, g_Z[p][d], 1.0f);
}

// Spectral MAC fused with inverse stage 6: accumulate each contiguous quad
// {4t+4096u+q} in registers, apply the unity-twiddle inverse butterfly, store.
template<bool FULL>
__device__ __forceinline__ void mac_stage6(float2* sm, int t, int mBlk, int p, int ncp) {
    #pragma unroll
    for (int u = 0; u < 4; ++u) {
        const int kq0 = 2 * t + 2048 * u;   // float4 index of bins {4t+4096u, +1}
        float2 a0 = make_float2(0.0f, 0.0f);
        float2 a1 = make_float2(0.0f, 0.0f);
        float2 a2 = make_float2(0.0f, 0.0f);
        float2 a3 = make_float2(0.0f, 0.0f);
        if (FULL) {
            #pragma unroll
            for (int c = 0; c < NPART; ++c) {
                const float4* Hc = (const float4*)g_H[c];
                const float4* Zc = (const float4*)g_Z[p][mBlk - c];
                float4 h0 = __ldg(Hc + kq0), h1 = __ldg(Hc + kq0 + 1);
                float4 z0 = __ldg(Zc + kq0), z1 = __ldg(Zc + kq0 + 1);
                a0 = cadd(a0, cmul(make_float2(h0.x, h0.y), make_float2(z0.x, z0.y)));
                a1 = cadd(a1, cmul(make_float2(h0.z, h0.w), make_float2(z0.z, z0.w)));
                a2 = cadd(a2, cmul(make_float2(h1.x, h1.y), make_float2(z1.x, z1.y)));
                a3 = cadd(a3, cmul(make_float2(h1.z, h1.w), make_float2(z1.z, z1.w)));
            }
        } else {
            for (int c = 0; c < ncp; ++c) {
                const float4* Hc = (const float4*)g_H[c];
                const float4* Zc = (const float4*)g_Z[p][mBlk - c];
                float4 h0 = __ldg(Hc + kq0), h1 = __ldg(Hc + kq0 + 1);
                float4 z0 = __ldg(Zc + kq0), z1 = __ldg(Zc + kq0 + 1);
                a0 = cadd(a0, cmul(make_float2(h0.x, h0.y), make_float2(z0.x, z0.y)));
                a1 = cadd(a1, cmul(make_float2(h0.z, h0.w), make_float2(z0.z, z0.w)));
                a2 = cadd(a2, cmul(make_float2(h1.x, h1.y), make_float2(z1.x, z1.y)));
                a3 = cadd(a3, cmul(make_float2(h1.z, h1.w), make_float2(z1.z, z1.w)));
            }
        }
        bfly_inv_nw(a0, a1, a2, a3);
        const int a = 4 * t + 4096 * u;
        sm[PADi(a)]     = a0;
        sm[PADi(a + 1)] = a1;
        sm[PADi(a + 2)] = a2;
        sm[PADi(a + 3)] = a3;
    }
}

__global__ void __launch_bounds__(NT, 1) y_kernel(const float* __restrict__ x,
                                                  const float* __restrict__ wet_param,
                                                  float* __restrict__ out) {
    extern __shared__ float2 sm[];
    const int mBlk = blockIdx.x;  // output block index
    const int p    = blockIdx.y;  // batch pair
    const int t    = threadIdx.x;

    if (mBlk >= NPART - 1) mac_stage6<true >(sm, t, mBlk, p, NPART);
    else                   mac_stage6<false>(sm, t, mBlk, p, mBlk + 1);
    __syncthreads();

    inv_mid_pass<4>(sm, t);     // stages 5 then 4
    __syncthreads();
    inv_mid_pass<2>(sm, t);     // stages 3 then 2
    __syncthreads();

    // Final inverse pass: stages 1 then 0 in registers, then write output mix.
    float2 v[16];
    #pragma unroll
    for (int j = 0; j < 16; ++j) v[j] = sm[PADi(t + 1024 * j)];
    inv_bflys<0>(v, t, 1024);

    const float wet = 1.0f / (1.0f + __expf(-wet_param[0]));
    const float dry = 1.0f - wet;
    const float* xe = x + (2 * p)     * T_LEN;
    const float* xo = x + (2 * p + 1) * T_LEN;
    float* oe = out + (2 * p)     * T_LEN;
    float* oo = out + (2 * p + 1) * T_LEN;

    // valid overlap-save outputs at natural positions [P, 2P) = j in [8,16)
    #pragma unroll
    for (int j = 8; j < 16; ++j) {
        int n = mBlk * P_HOP + t + 1024 * j - P_HOP;
        if (n < T_LEN) {
            oe[n] = fmaf(dry, xe[n], wet * v[j].x);
            oo[n] = fmaf(dry, xo[n], wet * v[j].y);
        }
    }
}

// ---------------- launcher ----------------
extern "C" void kernel_launch(void* const* d_in, const int* in_sizes, int n_in,
                              void* d_out, int out_size) {
    const float* x  = (const float*)d_in[0];
    const float* ir = (const float*)d_in[1];
    const float* wp = (const float*)d_in[2];
    float* out = (float*)d_out;

    const int smem = SMEM_F2 * sizeof(float2);   // 139264 B
    cudaFuncSetAttribute(zh_kernel, cudaFuncAttributeMaxDynamicSharedMemorySize, smem);
    cudaFuncSetAttribute(y_kernel,  cudaFuncAttributeMaxDynamicSharedMemorySize, smem);

    zh_kernel<<<dim3(NBLK, PAIRS + 1), NT, smem>>>(x, ir);
    y_kernel<<<dim3(NBLK, PAIRS), NT, smem>>>(x, wp, out);
}

// round 13
// speedup vs baseline: 1.1620x; 1.1620x over previous
#include <cuda_runtime.h>
#include <math.h>

// ---------------------------------------------------------------------------
// Frequency-domain partitioned convolution (uniform overlap-save), v6.
//   = v4's zh_kernel (measured: h folded into z launch, -12us)
//   + v3's y_kernel MAC (measured: coalesced 16B/thread loads)
//   + NEW: inverse stage 6 fused into the MAC via lane-pair shuffles
//     (partner exchange with shfl_xor, sign-selected butterfly halves,
//      same smem store addresses) — removes one 128KB smem round trip and
//     one __syncthreads from y WITHOUT touching the LDG pattern (the
//     mistake that made v4's fusion regress).
// ---------------------------------------------------------------------------

#define T_LEN   441000
#define PAIRS   16
#define IR_LEN  44100
#define P_HOP   8192
#define NFFT    16384
#define NBLK    54          // ceil(441000 / 8192)
#define NPART   6           // ceil(44100 / 8192)
#define NT      1024

__device__ __align__(16) float2 g_H[NPART][NFFT];
__device__ __align__(16) float2 g_Z[PAIRS][NBLK][NFFT];

__device__ __forceinline__ int PADi(int i) { return i + (i >> 4); }
#define SMEM_F2 (NFFT + (NFFT >> 4))        // padded float2 count

// ---------------- complex helpers ----------------
__device__ __forceinline__ float2 cadd(float2 a, float2 b) { return make_float2(a.x + b.x, a.y + b.y); }
__device__ __forceinline__ float2 csub(float2 a, float2 b) { return make_float2(a.x - b.x, a.y - b.y); }
__device__ __forceinline__ float2 cmul(float2 a, float2 b) {
    return make_float2(fmaf(a.x, b.x, -a.y * b.y), fmaf(a.x, b.y, a.y * b.x));
}
// a * conj(b)
__device__ __forceinline__ float2 cmulc(float2 a, float2 b) {
    return make_float2(fmaf(a.x, b.x, a.y * b.y), fmaf(a.y, b.x, -a.x * b.y));
}
__device__ __forceinline__ float2 sincosw(float ang) {
    float2 w; __sincosf(ang, &w.y, &w.x); return w;   // w = (cos, sin)
}
__device__ __forceinline__ void tw_pow(float2 w1, float2& w2, float2& w3) {
    w2 = cmul(w1, w1); w3 = cmul(w2, w1);
}

// ---------------- radix-4 butterflies ----------------
__device__ __forceinline__ void bfly_fwd_w(float2& a, float2& b, float2& c, float2& d,
                                           float2 w1, float2 w2, float2 w3) {
    float2 u0 = cadd(a, c), u1 = csub(a, c), u2 = cadd(b, d), t = csub(b, d);
    float2 u3 = make_float2(t.y, -t.x);   // -i*(b-d)
    a = cadd(u0, u2);
    b = cmul(cadd(u1, u3), w1);
    c = cmul(csub(u0, u2), w2);
    d = cmul(csub(u1, u3), w3);
}
__device__ __forceinline__ void bfly_fwd_nw(float2& a, float2& b, float2& c, float2& d) {
    float2 u0 = cadd(a, c), u1 = csub(a, c), u2 = cadd(b, d), t = csub(b, d);
    float2 u3 = make_float2(t.y, -t.x);
    a = cadd(u0, u2); b = cadd(u1, u3); c = csub(u0, u2); d = csub(u1, u3);
}
__device__ __forceinline__ void bfly_inv_w(float2& a, float2& b, float2& c, float2& d,
                                           float2 w1, float2 w2, float2 w3) {
    float2 y0 = a, y1 = cmulc(b, w1), y2 = cmulc(c, w2), y3 = cmulc(d, w3);
    float2 v0 = cadd(y0, y2), v2 = csub(y0, y2);
    float2 v1 = cadd(y1, y3), v3 = csub(y1, y3);
    float2 iv3 = make_float2(-v3.y, v3.x);  // i*v3
    a = cadd(v0, v1); b = cadd(v2, iv3); c = csub(v0, v1); d = csub(v2, iv3);
}

// ---------------- register pass: stages S and S+1 ----------------
template<int S>
__device__ __forceinline__ void fwd_bflys(float2 v[16], int r, int mq) {
    const float c = (-6.283185307179586f / (float)NFFT) * (float)(1 << (2 * S));
    float2 w1  = sincosw(c * (float)r);
    float2 rot = sincosw(c * (float)mq);
    #pragma unroll
    for (int j1 = 0; j1 < 4; ++j1) {
        float2 w2, w3; tw_pow(w1, w2, w3);
        bfly_fwd_w(v[j1], v[j1 + 4], v[j1 + 8], v[j1 + 12], w1, w2, w3);
        if (j1 < 3) w1 = cmul(w1, rot);
    }
    float2 s1 = sincosw(4.0f * c * (float)r);
    float2 s2, s3; tw_pow(s1, s2, s3);
    #pragma unroll
    for (int q = 0; q < 4; ++q)
        bfly_fwd_w(v[4 * q], v[4 * q + 1], v[4 * q + 2], v[4 * q + 3], s1, s2, s3);
}

template<int S>
__device__ __forceinline__ void inv_bflys(float2 v[16], int r, int mq) {
    const float c = (-6.283185307179586f / (float)NFFT) * (float)(1 << (2 * S));
    float2 s1 = sincosw(4.0f * c * (float)r);
    float2 s2, s3; tw_pow(s1, s2, s3);
    #pragma unroll
    for (int q = 0; q < 4; ++q)
        bfly_inv_w(v[4 * q], v[4 * q + 1], v[4 * q + 2], v[4 * q + 3], s1, s2, s3);
    float2 w1  = sincosw(c * (float)r);
    float2 rot = sincosw(c * (float)mq);
    #pragma unroll
    for (int j1 = 0; j1 < 4; ++j1) {
        float2 w2, w3; tw_pow(w1, w2, w3);
        bfly_inv_w(v[j1], v[j1 + 4], v[j1 + 8], v[j1 + 12], w1, w2, w3);
        if (j1 < 3) w1 = cmul(w1, rot);
    }
}

template<int S>
__device__ __forceinline__ void fwd_mid_pass(float2* sm, int t) {
    const int m   = 1 << (12 - 2 * S);
    const int mq  = m >> 2;
    const int r    = t & (mq - 1);
    const int base = ((t >> (10 - 2 * S)) << (14 - 2 * S)) + r;
    float2 v[16];
    #pragma unroll
    for (int j = 0; j < 16; ++j) v[j] = sm[PADi(base + j * mq)];
    fwd_bflys<S>(v, r, mq);
    #pragma unroll
    for (int j = 0; j < 16; ++j) sm[PADi(base + j * mq)] = v[j];
}

__device__ __forceinline__ void fwd_pass0_store(float2* sm, int t, float2 v[16]) {
    fwd_bflys<0>(v, t, 1024);
    #pragma unroll
    for (int j = 0; j < 16; ++j) sm[PADi(t + j * 1024)] = v[j];
}

// Forward stage 6 (unity twiddles, contiguous quads) + store to global (scaled).
__device__ __forceinline__ void fwd_stage6_store(const float2* sm, int t,
                                                 float2* __restrict__ dst, float s) {
    float4* dst4 = (float4*)dst;
    #pragma unroll
    for (int u = 0; u < 4; ++u) {
        int a = 4 * t + 4096 * u;
        float2 va = sm[PADi(a)], vb = sm[PADi(a + 1)];
        float2 vc = sm[PADi(a + 2)], vd = sm[PADi(a + 3)];
        bfly_fwd_nw(va, vb, vc, vd);
        dst4[(a >> 1)]     = make_float4(va.x * s, va.y * s, vb.x * s, vb.y * s);
        dst4[(a >> 1) + 1] = make_float4(vc.x * s, vc.y * s, vd.x * s, vd.y * s);
    }
}

template<int S>
__device__ __forceinline__ void inv_mid_pass(float2* sm, int t) {
    const int m   = 1 << (12 - 2 * S);
    const int mq  = m >> 2;
    const int r    = t & (mq - 1);
    const int base = ((t >> (10 - 2 * S)) << (14 - 2 * S)) + r;
    float2 v[16];
    #pragma unroll
    for (int j = 0; j < 16; ++j) v[j] = sm[PADi(base + j * mq)];
    inv_bflys<S>(v, r, mq);
    #pragma unroll
    for (int j = 0; j < 16; ++j) sm[PADi(base + j * mq)] = v[j];
}

// ---------------- kernels ----------------
// Combined forward transform: rows p < PAIRS produce Z blocks from x;
// row p == PAIRS (d < NPART) produces H partitions from ir.
__global__ void __launch_bounds__(NT, 1) zh_kernel(const float* __restrict__ x,
                                                   const float* __restrict__ ir) {
    extern __shared__ float2 sm[];
    const int d = blockIdx.x;
    const int p = blockIdx.y;
    const int t = threadIdx.x;
    const bool isH = (p == PAIRS);
    if (isH && d >= NPART) return;

    float2 v[16];
    if (isH) {
        #pragma unroll
        for (int j = 0; j < 16; ++j) {
            int k = t + 1024 * j;
            int tap = d * P_HOP + k;
            float val = (k < P_HOP && tap < IR_LEN) ? ir[tap] : 0.0f;
            v[j] = make_float2(val, 0.0f);
        }
    } else {
        const int base = d * P_HOP - P_HOP;   // covers [(d-1)P, (d+1)P)
        const float* xe = x + (2 * p)     * T_LEN;
        const float* xo = x + (2 * p + 1) * T_LEN;
        #pragma unroll
        for (int j = 0; j < 16; ++j) {
            int idx = base + t + 1024 * j;
            float re = 0.0f, im = 0.0f;
            if (idx >= 0 && idx < T_LEN) { re = xe[idx]; im = xo[idx]; }
            v[j] = make_float2(re, im);
        }
    }
    fwd_pass0_store(sm, t, v);
    __syncthreads();
    fwd_mid_pass<2>(sm, t);
    __syncthreads();
    fwd_mid_pass<4>(sm, t);
    __syncthreads();
    if (isH) fwd_stage6_store(sm, t, g_H[d], 1.0f / (float)NFFT);
    else     fwd_stage6_store(sm, t, g_Z[p][d], 1.0f);
}

// Spectral MAC (coalesced 16B/thread loads, unchanged) + inverse stage 6
// fused via lane-pair shuffles. Thread t holds bins {2kq, 2kq+1}; its
// stage-6 quad partner is lane t^1. Exchange the partner's pair with
// shfl_xor, compute this lane's half of the unity-twiddle butterfly
// (sign-selected), store to the SAME smem addresses as the unfused MAC.
template<bool FULL>
__device__ __forceinline__ void mac_stage6_shfl(float2* sm, int t, int mBlk, int p, int ncp) {
    const float sgn = (t & 1) ? -1.0f : 1.0f;
    #pragma unroll
    for (int j = 0; j < 8; ++j) {
        int kq = t + 1024 * j;              // float4 index -> complex 2kq, 2kq+1
        float2 a0 = make_float2(0.0f, 0.0f);
        float2 a1 = make_float2(0.0f, 0.0f);
        if (FULL) {
            #pragma unroll
            for (int c = 0; c < NPART; ++c) {
                float4 h = __ldg((const float4*)g_H[c] + kq);
                float4 z = __ldg((const float4*)g_Z[p][mBlk - c] + kq);
                a0 = cadd(a0, cmul(make_float2(h.x, h.y), make_float2(z.x, z.y)));
                a1 = cadd(a1, cmul(make_float2(h.z, h.w), make_float2(z.z, z.w)));
            }
        } else {
            for (int c = 0; c < ncp; ++c) {
                float4 h = __ldg((const float4*)g_H[c] + kq);
                float4 z = __ldg((const float4*)g_Z[p][mBlk - c] + kq);
                a0 = cadd(a0, cmul(make_float2(h.x, h.y), make_float2(z.x, z.y)));
                a1 = cadd(a1, cmul(make_float2(h.z, h.w), make_float2(z.z, z.w)));
            }
        }
        // partner's (a0, a1)
        float2 p0, p1;
        p0.x = __shfl_xor_sync(0xffffffffu, a0.x, 1);
        p0.y = __shfl_xor_sync(0xffffffffu, a0.y, 1);
        p1.x = __shfl_xor_sync(0xffffffffu, a1.x, 1);
        p1.y = __shfl_xor_sync(0xffffffffu, a1.y, 1);
        // quad inputs: A,B from even lane, C,D from odd lane
        // even lane: (A,B)=(a0,a1), (C,D)=(p0,p1); odd: (A,B)=(p0,p1), (C,D)=(a0,a1)
        float2 A  = (t & 1) ? p0 : a0;
        float2 B  = (t & 1) ? p1 : a1;
        float2 C  = (t & 1) ? a0 : p0;
        float2 D  = (t & 1) ? a1 : p1;
        float2 v0 = cadd(A, C), v2 = csub(A, C);
        float2 v1 = cadd(B, D), v3 = csub(B, D);
        float2 iv3 = make_float2(-v3.y, v3.x);          // i*v3
        // even lane outputs bins (4k,4k+1) = (v0+v1, v2+iv3)
        // odd  lane outputs bins (4k+2,4k+3) = (v0-v1, v2-iv3)
        float2 o0 = make_float2(fmaf(sgn, v1.x, v0.x), fmaf(sgn, v1.y, v0.y));
        float2 o1 = make_float2(fmaf(sgn, iv3.x, v2.x), fmaf(sgn, iv3.y, v2.y));
        sm[PADi(2 * kq)]     = o0;
        sm[PADi(2 * kq + 1)] = o1;
    }
}

__global__ void __launch_bounds__(NT, 1) y_kernel(const float* __restrict__ x,
                                                  const float* __restrict__ wet_param,
                                                  float* __restrict__ out) {
    extern __shared__ float2 sm[];
    const int mBlk = blockIdx.x;  // output block index
    const int p    = blockIdx.y;  // batch pair
    const int t    = threadIdx.x;

    if (mBlk >= NPART - 1) mac_stage6_shfl<true >(sm, t, mBlk, p, NPART);
    else                   mac_stage6_shfl<false>(sm, t, mBlk, p, mBlk + 1);
    __syncthreads();

    inv_mid_pass<4>(sm, t);     // stages 5 then 4
    __syncthreads();
    inv_mid_pass<2>(sm, t);     // stages 3 then 2
    __syncthreads();

    // Final inverse pass: stages 1 then 0 in registers, then write output mix.
    float2 v[16];
    #pragma unroll
    for (int j = 0; j < 16; ++j) v[j] = sm[PADi(t + 1024 * j)];
    inv_bflys<0>(v, t, 1024);

    const float wet = 1.0f / (1.0f + __expf(-wet_param[0]));
    const float dry = 1.0f - wet;
    const float* xe = x + (2 * p)     * T_LEN;
    const float* xo = x + (2 * p + 1) * T_LEN;
    float* oe = out + (2 * p)     * T_LEN;
    float* oo = out + (2 * p + 1) * T_LEN;

    // valid overlap-save outputs at natural positions [P, 2P) = j in [8,16)
    #pragma unroll
    for (int j = 8; j < 16; ++j) {
        int n = mBlk * P_HOP + t + 1024 * j - P_HOP;
        if (n < T_LEN) {
            oe[n] = fmaf(dry, xe[n], wet * v[j].x);
            oo[n] = fmaf(dry, xo[n], wet * v[j].y);
        }
    }
}

// ---------------- launcher ----------------
extern "C" void kernel_launch(void* const* d_in, const int* in_sizes, int n_in,
                              void* d_out, int out_size) {
    const float* x  = (const float*)d_in[0];
    const float* ir = (const float*)d_in[1];
    const float* wp = (const float*)d_in[2];
    float* out = (float*)d_out;

    const int smem = SMEM_F2 * sizeof(float2);   // 139264 B
    cudaFuncSetAttribute(zh_kernel, cudaFuncAttributeMaxDynamicSharedMemorySize, smem);
    cudaFuncSetAttribute(y_kernel,  cudaFuncAttributeMaxDynamicSharedMemorySize, smem);

    zh_kernel<<<dim3(NBLK, PAIRS + 1), NT, smem>>>(x, ir);
    y_kernel<<<dim3(NBLK, PAIRS), NT, smem>>>(x, wp, out);
}

// round 16
// speedup vs baseline: 1.1992x; 1.0320x over previous
#include <cuda_runtime.h>
#include <math.h>

// ---------------------------------------------------------------------------
// Frequency-domain partitioned convolution (uniform overlap-save), v7.
//   v6 + (1) zh: forward stage 6 fused into the [4,5] register pass via
//       4-lane shuffles (quad lives in 4 adjacent lanes after pass<4>) —
//       removes one smem round trip + sync from every forward FFT; spectra
//       stored in (A',C',B',D') quad order.
//   (2) y MAC inverse-stage-6 adapted to that order (local v0/v2 on even
//       lane, v1/v3 on odd; one pair exchange).
//   (3) inter-column twiddle rotation = constant -pi/8 in ALL passes
//       (hard-coded); s1 = (w1^2)^2 instead of sincos. 3 sincos/pass -> 1.
//   (4) y final stage-0 computes only the used (j>=8) outputs.
// ---------------------------------------------------------------------------

#define T_LEN   441000
#define PAIRS   16
#define IR_LEN  44100
#define P_HOP   8192
#define NFFT    16384
#define NBLK    54          // ceil(441000 / 8192)
#define NPART   6           // ceil(44100 / 8192)
#define NT      1024

__device__ __align__(16) float2 g_H[NPART][NFFT];
__device__ __align__(16) float2 g_Z[PAIRS][NBLK][NFFT];

__device__ __forceinline__ int PADi(int i) { return i + (i >> 4); }
#define SMEM_F2 (NFFT + (NFFT >> 4))        // padded float2 count

// rotation by one column step: angle c*mq = -2*pi*1024/16384 = -pi/8, ALL passes
#define ROT_RE 0.9238795325112867f
#define ROT_IM (-0.3826834323650898f)

// ---------------- complex helpers ----------------
__device__ __forceinline__ float2 cadd(float2 a, float2 b) { return make_float2(a.x + b.x, a.y + b.y); }
__device__ __forceinline__ float2 csub(float2 a, float2 b) { return make_float2(a.x - b.x, a.y - b.y); }
__device__ __forceinline__ float2 cmul(float2 a, float2 b) {
    return make_float2(fmaf(a.x, b.x, -a.y * b.y), fmaf(a.x, b.y, a.y * b.x));
}
// a * conj(b)
__device__ __forceinline__ float2 cmulc(float2 a, float2 b) {
    return make_float2(fmaf(a.x, b.x, a.y * b.y), fmaf(a.y, b.x, -a.x * b.y));
}
__device__ __forceinline__ float2 sincosw(float ang) {
    float2 w; __sincosf(ang, &w.y, &w.x); return w;   // w = (cos, sin)
}
__device__ __forceinline__ void tw_pow(float2 w1, float2& w2, float2& w3) {
    w2 = cmul(w1, w1); w3 = cmul(w2, w1);
}

// ---------------- radix-4 butterflies ----------------
__device__ __forceinline__ void bfly_fwd_w(float2& a, float2& b, float2& c, float2& d,
                                           float2 w1, float2 w2, float2 w3) {
    float2 u0 = cadd(a, c), u1 = csub(a, c), u2 = cadd(b, d), t = csub(b, d);
    float2 u3 = make_float2(t.y, -t.x);   // -i*(b-d)
    a = cadd(u0, u2);
    b = cmul(cadd(u1, u3), w1);
    c = cmul(csub(u0, u2), w2);
    d = cmul(csub(u1, u3), w3);
}
__device__ __forceinline__ void bfly_inv_w(float2& a, float2& b, float2& c, float2& d,
                                           float2 w1, float2 w2, float2 w3) {
    float2 y0 = a, y1 = cmulc(b, w1), y2 = cmulc(c, w2), y3 = cmulc(d, w3);
    float2 v0 = cadd(y0, y2), v2 = csub(y0, y2);
    float2 v1 = cadd(y1, y3), v3 = csub(y1, y3);
    float2 iv3 = make_float2(-v3.y, v3.x);  // i*v3
    a = cadd(v0, v1); b = cadd(v2, iv3); c = csub(v0, v1); d = csub(v2, iv3);
}

// ---------------- register pass: stages S and S+1 ----------------
template<int S>
__device__ __forceinline__ void fwd_bflys(float2 v[16], int r, int mq) {
    const float c = (-6.283185307179586f / (float)NFFT) * (float)(1 << (2 * S));
    float2 w1  = sincosw(c * (float)r);
    const float2 rot = make_float2(ROT_RE, ROT_IM);
    float2 w2i = cmul(w1, w1);
    float2 s1  = cmul(w2i, w2i);          // = sincos(4*c*r)
    #pragma unroll
    for (int j1 = 0; j1 < 4; ++j1) {
        float2 w2, w3; tw_pow(w1, w2, w3);
        bfly_fwd_w(v[j1], v[j1 + 4], v[j1 + 8], v[j1 + 12], w1, w2, w3);
        if (j1 < 3) w1 = cmul(w1, rot);
    }
    float2 s2, s3; tw_pow(s1, s2, s3);
    #pragma unroll
    for (int q = 0; q < 4; ++q)
        bfly_fwd_w(v[4 * q], v[4 * q + 1], v[4 * q + 2], v[4 * q + 3], s1, s2, s3);
}

template<int S>
__device__ __forceinline__ void inv_bflys(float2 v[16], int r, int mq) {
    const float c = (-6.283185307179586f / (float)NFFT) * (float)(1 << (2 * S));
    float2 w1  = sincosw(c * (float)r);
    float2 w2i = cmul(w1, w1);
    float2 s1  = cmul(w2i, w2i);
    float2 s2, s3; tw_pow(s1, s2, s3);
    #pragma unroll
    for (int q = 0; q < 4; ++q)
        bfly_inv_w(v[4 * q], v[4 * q + 1], v[4 * q + 2], v[4 * q + 3], s1, s2, s3);
    const float2 rot = make_float2(ROT_RE, ROT_IM);
    #pragma unroll
    for (int j1 = 0; j1 < 4; ++j1) {
        float2 w2, w3; tw_pow(w1, w2, w3);
        bfly_inv_w(v[j1], v[j1 + 4], v[j1 + 8], v[j1 + 12], w1, w2, w3);
        if (j1 < 3) w1 = cmul(w1, rot);
    }
}

template<int S>
__device__ __forceinline__ void fwd_mid_pass(float2* sm, int t) {
    const int m   = 1 << (12 - 2 * S);
    const int mq  = m >> 2;
    const int r    = t & (mq - 1);
    const int base = ((t >> (10 - 2 * S)) << (14 - 2 * S)) + r;
    float2 v[16];
    #pragma unroll
    for (int j = 0; j < 16; ++j) v[j] = sm[PADi(base + j * mq)];
    fwd_bflys<S>(v, r, mq);
    #pragma unroll
    for (int j = 0; j < 16; ++j) sm[PADi(base + j * mq)] = v[j];
}

__device__ __forceinline__ void fwd_pass0_store(float2* sm, int t, float2 v[16]) {
    fwd_bflys<0>(v, t, 1024);
    #pragma unroll
    for (int j = 0; j < 16; ++j) sm[PADi(t + j * 1024)] = v[j];
}

// Stage 6 fused after fwd_bflys<4> (thread t holds quad position t&3 of
// quads ((t>>2)<<4)+j, i.e. the quad spans 4 adjacent lanes).
// Two shfl_xor steps; result stored directly to gmem in (A',C',B',D') order
// at the thread's own element index base4 + 4j.
__device__ __forceinline__ void fwd_stage6_shfl_store(float2 v[16], int t,
                                                      float2* __restrict__ dst, float s) {
    const int l = t & 3;
    const float sg1 = (l & 2) ? -1.0f : 1.0f;
    const float sg2 = (l & 1) ? -1.0f : 1.0f;
    const int base4 = ((t >> 2) << 6) + l;
    #pragma unroll
    for (int j = 0; j < 16; ++j) {
        float2 own = v[j];
        float2 p;
        p.x = __shfl_xor_sync(0xffffffffu, own.x, 2);
        p.y = __shfl_xor_sync(0xffffffffu, own.y, 2);
        float2 r = make_float2(fmaf(sg1, own.x, p.x), fmaf(sg1, own.y, p.y));
        // lane 3 applies -i to (b-d)
        float2 y = (l == 3) ? make_float2(r.y, -r.x) : r;
        float2 q;
        q.x = __shfl_xor_sync(0xffffffffu, y.x, 1);
        q.y = __shfl_xor_sync(0xffffffffu, y.y, 1);
        float2 o = make_float2(fmaf(sg2, y.x, q.x), fmaf(sg2, y.y, q.y));
        dst[base4 + 4 * j] = make_float2(o.x * s, o.y * s);
    }
}

template<int S>
__device__ __forceinline__ void inv_mid_pass(float2* sm, int t) {
    const int m   = 1 << (12 - 2 * S);
    const int mq  = m >> 2;
    const int r    = t & (mq - 1);
    const int base = ((t >> (10 - 2 * S)) << (14 - 2 * S)) + r;
    float2 v[16];
    #pragma unroll
    for (int j = 0; j < 16; ++j) v[j] = sm[PADi(base + j * mq)];
    inv_bflys<S>(v, r, mq);
    #pragma unroll
    for (int j = 0; j < 16; ++j) sm[PADi(base + j * mq)] = v[j];
}

// Final inverse pass (stages 1 then 0): stage 0 computes only the c,d
// outputs (j = 8..15) — the only ones consumed by the epilogue.
__device__ __forceinline__ void inv_final_bflys(float2 v[16], int r) {
    const float c = -6.283185307179586f / (float)NFFT;
    float2 w1  = sincosw(c * (float)r);
    float2 w2i = cmul(w1, w1);
    float2 s1  = cmul(w2i, w2i);
    float2 s2, s3; tw_pow(s1, s2, s3);
    #pragma unroll
    for (int q = 0; q < 4; ++q)
        bfly_inv_w(v[4 * q], v[4 * q + 1], v[4 * q + 2], v[4 * q + 3], s1, s2, s3);
    const float2 rot = make_float2(ROT_RE, ROT_IM);
    #pragma unroll
    for (int j1 = 0; j1 < 4; ++j1) {
        float2 w2, w3; tw_pow(w1, w2, w3);
        float2 y0 = v[j1];
        float2 y1 = cmulc(v[j1 + 4],  w1);
        float2 y2 = cmulc(v[j1 + 8],  w2);
        float2 y3 = cmulc(v[j1 + 12], w3);
        float2 v0 = cadd(y0, y2), v2 = csub(y0, y2);
        float2 v1 = cadd(y1, y3), v3 = csub(y1, y3);
        float2 iv3 = make_float2(-v3.y, v3.x);
        v[j1 + 8]  = csub(v0, v1);     // c output
        v[j1 + 12] = csub(v2, iv3);    // d output
        if (j1 < 3) w1 = cmul(w1, rot);
    }
}

// ---------------- kernels ----------------
// Combined forward transform: rows p < PAIRS produce Z blocks from x;
// row p == PAIRS (d < NPART) produces H partitions from ir.
__global__ void __launch_bounds__(NT, 1) zh_kernel(const float* __restrict__ x,
                                                   const float* __restrict__ ir) {
    extern __shared__ float2 sm[];
    const int d = blockIdx.x;
    const int p = blockIdx.y;
    const int t = threadIdx.x;
    const bool isH = (p == PAIRS);
    if (isH && d >= NPART) return;

    float2 v[16];
    if (isH) {
        #pragma unroll
        for (int j = 0; j < 16; ++j) {
            int k = t + 1024 * j;
            int tap = d * P_HOP + k;
            float val = (k < P_HOP && tap < IR_LEN) ? ir[tap] : 0.0f;
            v[j] = make_float2(val, 0.0f);
        }
    } else {
        const int base = d * P_HOP - P_HOP;   // covers [(d-1)P, (d+1)P)
        const float* xe = x + (2 * p)     * T_LEN;
        const float* xo = x + (2 * p + 1) * T_LEN;
        #pragma unroll
        for (int j = 0; j < 16; ++j) {
            int idx = base + t + 1024 * j;
            float re = 0.0f, im = 0.0f;
            if (idx >= 0 && idx < T_LEN) { re = xe[idx]; im = xo[idx]; }
            v[j] = make_float2(re, im);
        }
    }
    fwd_pass0_store(sm, t, v);
    __syncthreads();
    fwd_mid_pass<2>(sm, t);
    __syncthreads();

    // pass [4,5] load + butterflies in registers, then fused stage 6 + STG
    {
        const int r4   = t & 3;
        const int base = ((t >> 2) << 6) + r4;
        float2 w[16];
        #pragma unroll
        for (int j = 0; j < 16; ++j) w[j] = sm[PADi(base + 4 * j)];
        fwd_bflys<4>(w, r4, 4);
        float2* dst = isH ? g_H[d] : g_Z[p][d];
        const float s = isH ? (1.0f / (float)NFFT) : 1.0f;
        fwd_stage6_shfl_store(w, t, dst, s);
    }
}

// Spectral MAC (coalesced 16B/thread loads) + inverse stage 6 in the
// permuted (A',C',B',D') quad order: even lane holds (A,C) -> v0,v2 local;
// odd lane holds (B,D) -> v1,v3 local; one pair exchange completes the
// butterfly; stores to natural bin positions.
template<bool FULL>
__device__ __forceinline__ void mac_stage6_shfl(float2* sm, int t, int mBlk, int p, int ncp) {
    const bool odd = (t & 1);
    #pragma unroll
    for (int j = 0; j < 8; ++j) {
        int kq = t + 1024 * j;              // float4 index -> elements 2kq, 2kq+1
        float2 a0 = make_float2(0.0f, 0.0f);
        float2 a1 = make_float2(0.0f, 0.0f);
        if (FULL) {
            #pragma unroll
            for (int c = 0; c < NPART; ++c) {
                float4 h = __ldg((const float4*)g_H[c] + kq);
                float4 z = __ldg((const float4*)g_Z[p][mBlk - c] + kq);
                a0 = cadd(a0, cmul(make_float2(h.x, h.y), make_float2(z.x, z.y)));
                a1 = cadd(a1, cmul(make_float2(h.z, h.w), make_float2(z.z, z.w)));
            }
        } else {
            for (int c = 0; c < ncp; ++c) {
                float4 h = __ldg((const float4*)g_H[c] + kq);
                float4 z = __ldg((const float4*)g_Z[p][mBlk - c] + kq);
                a0 = cadd(a0, cmul(make_float2(h.x, h.y), make_float2(z.x, z.y)));
                a1 = cadd(a1, cmul(make_float2(h.z, h.w), make_float2(z.z, z.w)));
            }
        }
        // even lane: (a0,a1) = (A, C) -> v0 = A+C, v2 = A-C
        // odd  lane: (a0,a1) = (B, D) -> v1 = B+D, v3 = B-D
        float2 sum = cadd(a0, a1);
        float2 dif = csub(a0, a1);
        float2 ps, pd;
        ps.x = __shfl_xor_sync(0xffffffffu, sum.x, 1);
        ps.y = __shfl_xor_sync(0xffffffffu, sum.y, 1);
        pd.x = __shfl_xor_sync(0xffffffffu, dif.x, 1);
        pd.y = __shfl_xor_sync(0xffffffffu, dif.y, 1);
        float2 o0, o1;
        if (!odd) {
            // bins (4m, 4m+1): A2 = v0+v1,  B2 = v2 + i*v3
            o0 = cadd(sum, ps);
            o1 = make_float2(dif.x - pd.y, dif.y + pd.x);
        } else {
            // bins (4m+2, 4m+3): C2 = v0-v1,  D2 = v2 - i*v3
            o0 = csub(ps, sum);
            o1 = make_float2(pd.x + dif.y, pd.y - dif.x);
        }
        sm[PADi(2 * kq)]     = o0;
        sm[PADi(2 * kq + 1)] = o1;
    }
}

__global__ void __launch_bounds__(NT, 1) y_kernel(const float* __restrict__ x,
                                                  const float* __restrict__ wet_param,
                                                  float* __restrict__ out) {
    extern __shared__ float2 sm[];
    const int mBlk = blockIdx.x;  // output block index
    const int p    = blockIdx.y;  // batch pair
    const int t    = threadIdx.x;

    if (mBlk >= NPART - 1) mac_stage6_shfl<true >(sm, t, mBlk, p, NPART);
    else                   mac_stage6_shfl<false>(sm, t, mBlk, p, mBlk + 1);
    __syncthreads();

    inv_mid_pass<4>(sm, t);     // stages 5 then 4
    __syncthreads();
    inv_mid_pass<2>(sm, t);     // stages 3 then 2
    __syncthreads();

    // Final inverse pass: stage 1 full, stage 0 only for j>=8 outputs.
    float2 v[16];
    #pragma unroll
    for (int j = 0; j < 16; ++j) v[j] = sm[PADi(t + 1024 * j)];
    inv_final_bflys(v, t);

    const float wet = 1.0f / (1.0f + __expf(-wet_param[0]));
    const float dry = 1.0f - wet;
    const float* xe = x + (2 * p)     * T_LEN;
    const float* xo = x + (2 * p + 1) * T_LEN;
    float* oe = out + (2 * p)     * T_LEN;
    float* oo = out + (2 * p + 1) * T_LEN;

    // valid overlap-save outputs at natural positions [P, 2P) = j in [8,16)
    #pragma unroll
    for (int j = 8; j < 16; ++j) {
        int n = mBlk * P_HOP + t + 1024 * j - P_HOP;
        if (n < T_LEN) {
            oe[n] = fmaf(dry, xe[n], wet * v[j].x);
            oo[n] = fmaf(dry, xo[n], wet * v[j].y);
        }
    }
}

// ---------------- launcher ----------------
extern "C" void kernel_launch(void* const* d_in, const int* in_sizes, int n_in,
                              void* d_out, int out_size) {
    const float* x  = (const float*)d_in[0];
    const float* ir = (const float*)d_in[1];
    const float* wp = (const float*)d_in[2];
    float* out = (float*)d_out;

    const int smem = SMEM_F2 * sizeof(float2);   // 139264 B
    cudaFuncSetAttribute(zh_kernel, cudaFuncAttributeMaxDynamicSharedMemorySize, smem);
    cudaFuncSetAttribute(y_kernel,  cudaFuncAttributeMaxDynamicSharedMemorySize, smem);

    zh_kernel<<<dim3(NBLK, PAIRS + 1), NT, smem>>>(x, ir);
    y_kernel<<<dim3(NBLK, PAIRS), NT, smem>>>(x, wp, out);
}